// round 1
// baseline (speedup 1.0000x reference)
#include <cuda_runtime.h>
#include <math.h>

#define T_TOTAL 131072
#define CDIM 256
#define MDIM 128
#define TILE 128

#define SA_STRIDE 129   // [k][x] transposed tiles
#define PS_STRIDE 129   // [r][m]
#define Q2_STRIDE 132   // [r][c], multiple of 4 for float4 stores

// region sizes in floats
#define REG_B 16512                 // 128*129
#define REG_A1 16896                // max(128*129, 128*132)  (phase1 A region)
#define REG_A2 32768                // 128*256 (phase2: full new_mem)
#define SMEM1_BYTES ((REG_B + REG_A1) * 4)   // 133632
#define SMEM2_BYTES ((REG_B + REG_A2) * 4)   // 197120

#define OUT_OFF   0
#define ATTN_OFF  ((size_t)T_TOTAL * 2 * CDIM)                 // 67108864
#define NM_OFF    (ATTN_OFF + (size_t)T_TOTAL * MDIM)          // 83886080

__device__ float g_add_mem[MDIM * CDIM];
__device__ float g_new_mem[MDIM * CDIM];

__global__ void zero_kernel() {
    int i = blockIdx.x * blockDim.x + threadIdx.x;
    if (i < MDIM * CDIM) g_add_mem[i] = 0.0f;
}

// ---------------------------------------------------------------------------
// Phase 1: per 128-row tile: S = Q@mem^T, softmax(+clamp 1e-8) -> P,
// then atomicAdd partial P^T@Q into g_add_mem.
// ---------------------------------------------------------------------------
__global__ void __launch_bounds__(256, 1)
phase1_kernel(const float* __restrict__ q, const float* __restrict__ mem) {
    extern __shared__ float sm[];
    float* B = sm;            // mem_s [k][m] (stride 129) -> later Ps [r][m]
    float* A = sm + REG_B;    // Qs [k][r] (stride 129) -> later Qs2 [r][c] (stride 132)

    const int tid = threadIdx.x;
    const int tr = tid >> 4;          // 0..15
    const int tc = tid & 15;          // 0..15
    const int row0 = blockIdx.x * TILE;

    float S[8][8];
#pragma unroll
    for (int i = 0; i < 8; i++)
#pragma unroll
        for (int j = 0; j < 8; j++) S[i][j] = 0.0f;

    // ---- Stage A: S accumulation over k in two 128-chunks ----
    for (int kc = 0; kc < 2; kc++) {
#pragma unroll
        for (int l = 0; l < 16; l++) {
            int e = l * 256 + tid;          // float4 index, 0..4095
            int r = e >> 5;
            int k4 = e & 31;
            float4 v = *(const float4*)(q + (size_t)(row0 + r) * CDIM + kc * 128 + k4 * 4);
            A[(4 * k4 + 0) * SA_STRIDE + r] = v.x;
            A[(4 * k4 + 1) * SA_STRIDE + r] = v.y;
            A[(4 * k4 + 2) * SA_STRIDE + r] = v.z;
            A[(4 * k4 + 3) * SA_STRIDE + r] = v.w;
        }
#pragma unroll
        for (int l = 0; l < 16; l++) {
            int e = l * 256 + tid;
            int m = e >> 5;
            int k4 = e & 31;
            float4 v = *(const float4*)(mem + (size_t)m * CDIM + kc * 128 + k4 * 4);
            B[(4 * k4 + 0) * SA_STRIDE + m] = v.x;
            B[(4 * k4 + 1) * SA_STRIDE + m] = v.y;
            B[(4 * k4 + 2) * SA_STRIDE + m] = v.z;
            B[(4 * k4 + 3) * SA_STRIDE + m] = v.w;
        }
        __syncthreads();
#pragma unroll 4
        for (int k = 0; k < 128; k++) {
            float a[8], b[8];
#pragma unroll
            for (int i = 0; i < 8; i++) a[i] = A[k * SA_STRIDE + tr + 16 * i];
#pragma unroll
            for (int j = 0; j < 8; j++) b[j] = B[k * SA_STRIDE + tc + 16 * j];
#pragma unroll
            for (int i = 0; i < 8; i++)
#pragma unroll
                for (int j = 0; j < 8; j++) S[i][j] = fmaf(a[i], b[j], S[i][j]);
        }
        __syncthreads();
    }

    // ---- Stage B: softmax over m (row = tr+16i owned by the 16 lanes sharing tr) ----
    float P[8][8];
#pragma unroll
    for (int i = 0; i < 8; i++) {
        float mx = -1e30f;
#pragma unroll
        for (int j = 0; j < 8; j++) mx = fmaxf(mx, S[i][j]);
#pragma unroll
        for (int o = 8; o >= 1; o >>= 1) mx = fmaxf(mx, __shfl_xor_sync(0xffffffffu, mx, o));
        float sum = 0.0f;
#pragma unroll
        for (int j = 0; j < 8; j++) { P[i][j] = __expf(S[i][j] - mx); sum += P[i][j]; }
#pragma unroll
        for (int o = 8; o >= 1; o >>= 1) sum += __shfl_xor_sync(0xffffffffu, sum, o);
        float inv = 1.0f / sum;
#pragma unroll
        for (int j = 0; j < 8; j++) P[i][j] = fmaxf(P[i][j] * inv, 1e-8f);
    }
    // write P to smem (Ps[r][m])
#pragma unroll
    for (int i = 0; i < 8; i++)
#pragma unroll
        for (int j = 0; j < 8; j++)
            B[(tr + 16 * i) * PS_STRIDE + tc + 16 * j] = P[i][j];
    __syncthreads();

    // ---- Stage C: add_mem_partial[m][c] = sum_r P[r][m]*Q[r][c], atomicAdd ----
    for (int cc = 0; cc < 2; cc++) {
#pragma unroll
        for (int l = 0; l < 16; l++) {
            int e = l * 256 + tid;
            int r = e >> 5;
            int c4 = e & 31;
            float4 v = *(const float4*)(q + (size_t)(row0 + r) * CDIM + cc * 128 + c4 * 4);
            *(float4*)(A + r * Q2_STRIDE + c4 * 4) = v;
        }
        __syncthreads();
        float acc[8][8];
#pragma unroll
        for (int i = 0; i < 8; i++)
#pragma unroll
            for (int j = 0; j < 8; j++) acc[i][j] = 0.0f;
#pragma unroll 4
        for (int r = 0; r < 128; r++) {
            float p[8], qq[8];
#pragma unroll
            for (int i = 0; i < 8; i++) p[i] = B[r * PS_STRIDE + tr + 16 * i];
#pragma unroll
            for (int j = 0; j < 8; j++) qq[j] = A[r * Q2_STRIDE + tc + 16 * j];
#pragma unroll
            for (int i = 0; i < 8; i++)
#pragma unroll
                for (int j = 0; j < 8; j++) acc[i][j] = fmaf(p[i], qq[j], acc[i][j]);
        }
#pragma unroll
        for (int i = 0; i < 8; i++)
#pragma unroll
            for (int j = 0; j < 8; j++)
                atomicAdd(&g_add_mem[(tr + 16 * i) * CDIM + cc * 128 + tc + 16 * j], acc[i][j]);
        __syncthreads();
    }
}

// ---------------------------------------------------------------------------
// Gate + memory update + row L2-normalize (tiny)
// ---------------------------------------------------------------------------
__global__ void __launch_bounds__(256)
gate_kernel(const float* __restrict__ mem,
            const float* __restrict__ U_w, const float* __restrict__ U_b,
            const float* __restrict__ W_w, const float* __restrict__ W_b,
            float* __restrict__ out_nm) {
    __shared__ float mrow[CDIM];
    __shared__ float arow[CDIM];
    __shared__ float red[256];
    const int m = blockIdx.x;
    const int c = threadIdx.x;

    mrow[c] = mem[(size_t)m * CDIM + c];
    arow[c] = g_add_mem[(size_t)m * CDIM + c];
    __syncthreads();

    float acc = U_b[c] + W_b[c];
    const float* uw = U_w + (size_t)c * CDIM;
    const float* ww = W_w + (size_t)c * CDIM;
#pragma unroll 8
    for (int k = 0; k < CDIM; k++) acc = fmaf(mrow[k], uw[k], fmaf(arow[k], ww[k], acc));

    float gate = 1.0f / (1.0f + __expf(-acc));
    float mv = mrow[c], av = arow[c];
    float nm = 0.9f * mv + 0.1f * ((1.0f - gate) * mv + gate * av);

    red[c] = nm * nm;
    __syncthreads();
    for (int s = 128; s > 0; s >>= 1) {
        if (c < s) red[c] += red[c + s];
        __syncthreads();
    }
    float norm = sqrtf(red[0]);
    float inv = 1.0f / fmaxf(norm, 1e-12f);
    float v = nm * inv;
    g_new_mem[(size_t)m * CDIM + c] = v;
    out_nm[(size_t)m * CDIM + c] = v;
}

// ---------------------------------------------------------------------------
// Phase 2: S = Q@new_mem^T, softmax -> hard_shrink_relu -> L1 norm -> attn,
// add_memory = attn@new_mem; also copies q into out[:, :256].
// ---------------------------------------------------------------------------
__global__ void __launch_bounds__(256, 1)
phase2_kernel(const float* __restrict__ q, float* __restrict__ out,
              float* __restrict__ attn_out) {
    extern __shared__ float sm[];
    float* B = sm;            // nm chunk [k][m] -> later Ps [r][m]
    float* A = sm + REG_B;    // Qs [k][r] -> later full new_mem [m][c] (stride 256)

    const int tid = threadIdx.x;
    const int tr = tid >> 4;
    const int tc = tid & 15;
    const int row0 = blockIdx.x * TILE;

    float S[8][8];
#pragma unroll
    for (int i = 0; i < 8; i++)
#pragma unroll
        for (int j = 0; j < 8; j++) S[i][j] = 0.0f;

    for (int kc = 0; kc < 2; kc++) {
#pragma unroll
        for (int l = 0; l < 16; l++) {
            int e = l * 256 + tid;
            int r = e >> 5;
            int k4 = e & 31;
            float4 v = *(const float4*)(q + (size_t)(row0 + r) * CDIM + kc * 128 + k4 * 4);
            A[(4 * k4 + 0) * SA_STRIDE + r] = v.x;
            A[(4 * k4 + 1) * SA_STRIDE + r] = v.y;
            A[(4 * k4 + 2) * SA_STRIDE + r] = v.z;
            A[(4 * k4 + 3) * SA_STRIDE + r] = v.w;
            // free q-copy into out[:, 0:256]
            *(float4*)(out + (size_t)(row0 + r) * (2 * CDIM) + kc * 128 + k4 * 4) = v;
        }
#pragma unroll
        for (int l = 0; l < 16; l++) {
            int e = l * 256 + tid;
            int m = e >> 5;
            int k4 = e & 31;
            float4 v = *(const float4*)(g_new_mem + (size_t)m * CDIM + kc * 128 + k4 * 4);
            B[(4 * k4 + 0) * SA_STRIDE + m] = v.x;
            B[(4 * k4 + 1) * SA_STRIDE + m] = v.y;
            B[(4 * k4 + 2) * SA_STRIDE + m] = v.z;
            B[(4 * k4 + 3) * SA_STRIDE + m] = v.w;
        }
        __syncthreads();
#pragma unroll 4
        for (int k = 0; k < 128; k++) {
            float a[8], b[8];
#pragma unroll
            for (int i = 0; i < 8; i++) a[i] = A[k * SA_STRIDE + tr + 16 * i];
#pragma unroll
            for (int j = 0; j < 8; j++) b[j] = B[k * SA_STRIDE + tc + 16 * j];
#pragma unroll
            for (int i = 0; i < 8; i++)
#pragma unroll
                for (int j = 0; j < 8; j++) S[i][j] = fmaf(a[i], b[j], S[i][j]);
        }
        __syncthreads();
    }

    // softmax -> hard_shrink_relu -> L1 normalize
    float P[8][8];
#pragma unroll
    for (int i = 0; i < 8; i++) {
        float mx = -1e30f;
#pragma unroll
        for (int j = 0; j < 8; j++) mx = fmaxf(mx, S[i][j]);
#pragma unroll
        for (int o = 8; o >= 1; o >>= 1) mx = fmaxf(mx, __shfl_xor_sync(0xffffffffu, mx, o));
        float sum = 0.0f;
#pragma unroll
        for (int j = 0; j < 8; j++) { P[i][j] = __expf(S[i][j] - mx); sum += P[i][j]; }
#pragma unroll
        for (int o = 8; o >= 1; o >>= 1) sum += __shfl_xor_sync(0xffffffffu, sum, o);
        float inv = 1.0f / sum;
        float l1 = 0.0f;
#pragma unroll
        for (int j = 0; j < 8; j++) {
            float a = P[i][j] * inv;
            float d = a - 0.0025f;
            float a2 = fmaxf(d, 0.0f) * a / (fabsf(d) + 1e-12f);
            P[i][j] = a2;
            l1 += a2;  // a2 >= 0
        }
#pragma unroll
        for (int o = 8; o >= 1; o >>= 1) l1 += __shfl_xor_sync(0xffffffffu, l1, o);
        float invl = 1.0f / fmaxf(l1, 1e-12f);
#pragma unroll
        for (int j = 0; j < 8; j++) P[i][j] *= invl;
    }
    // write attn to gmem + Ps to smem
#pragma unroll
    for (int i = 0; i < 8; i++) {
        int r = tr + 16 * i;
#pragma unroll
        for (int j = 0; j < 8; j++) {
            int m = tc + 16 * j;
            B[r * PS_STRIDE + m] = P[i][j];
            attn_out[(size_t)(row0 + r) * MDIM + m] = P[i][j];
        }
    }
    __syncthreads();

    // load full new_mem [m][c] into A (stride 256)
#pragma unroll
    for (int l = 0; l < 32; l++) {
        int e = l * 256 + tid;  // float4 index, 0..8191
        int mm = e >> 6;
        int c4 = e & 63;
        *(float4*)(A + mm * 256 + c4 * 4) = *(const float4*)(g_new_mem + (size_t)mm * 256 + c4 * 4);
    }
    __syncthreads();

    // add_memory[r][c] = sum_m P[r][m] * nm[m][c]
    for (int cc = 0; cc < 2; cc++) {
        float acc[8][8];
#pragma unroll
        for (int i = 0; i < 8; i++)
#pragma unroll
            for (int j = 0; j < 8; j++) acc[i][j] = 0.0f;
#pragma unroll 4
        for (int m = 0; m < 128; m++) {
            float p[8], b[8];
#pragma unroll
            for (int i = 0; i < 8; i++) p[i] = B[(tr + 16 * i) * PS_STRIDE + m];
#pragma unroll
            for (int j = 0; j < 8; j++) b[j] = A[m * 256 + cc * 128 + tc + 16 * j];
#pragma unroll
            for (int i = 0; i < 8; i++)
#pragma unroll
                for (int j = 0; j < 8; j++) acc[i][j] = fmaf(p[i], b[j], acc[i][j]);
        }
#pragma unroll
        for (int i = 0; i < 8; i++) {
            int r = row0 + tr + 16 * i;
#pragma unroll
            for (int j = 0; j < 8; j++) {
                int c = cc * 128 + tc + 16 * j;
                out[(size_t)r * (2 * CDIM) + CDIM + c] = acc[i][j];
            }
        }
    }
}

// ---------------------------------------------------------------------------
extern "C" void kernel_launch(void* const* d_in, const int* in_sizes, int n_in,
                              void* d_out, int out_size) {
    const float* q   = (const float*)d_in[0];
    const float* mem = (const float*)d_in[1];
    const float* U_w = (const float*)d_in[2];
    const float* U_b = (const float*)d_in[3];
    const float* W_w = (const float*)d_in[4];
    const float* W_b = (const float*)d_in[5];
    float* out = (float*)d_out;
    float* attn_out = out + ATTN_OFF;
    float* nm_out = out + NM_OFF;

    cudaFuncSetAttribute(phase1_kernel, cudaFuncAttributeMaxDynamicSharedMemorySize, SMEM1_BYTES);
    cudaFuncSetAttribute(phase2_kernel, cudaFuncAttributeMaxDynamicSharedMemorySize, SMEM2_BYTES);

    zero_kernel<<<(MDIM * CDIM + 255) / 256, 256>>>();
    phase1_kernel<<<T_TOTAL / TILE, 256, SMEM1_BYTES>>>(q, mem);
    gate_kernel<<<MDIM, 256>>>(mem, U_w, U_b, W_w, W_b, nm_out);
    phase2_kernel<<<T_TOTAL / TILE, 256, SMEM2_BYTES>>>(q, out, attn_out);
}